// round 4
// baseline (speedup 1.0000x reference)
#include <cuda_runtime.h>
#include <cstdint>
#include <cstddef>

#define TL 512
#define NB 2048
#define NB16 (NB*16)
#define FULL 0xffffffffu

// scratch: hproj_seq and z_seq, each T*B*16 floats = 64 MiB
__device__ float g_hproj[(size_t)TL * NB * 16];
__device__ float g_zseq[(size_t)TL * NB * 16];

__device__ __forceinline__ float sigf(float x){
  return __fdividef(1.f, 1.f + __expf(-x));
}
__device__ __forceinline__ float tanh_fast(float x){
  return __fdividef(2.f, 1.f + __expf(-2.f * x)) - 1.f;
}

__device__ __forceinline__ void ldv16(const float* p, float v[16]){
  #pragma unroll
  for (int i = 0; i < 4; i++){
    float4 q = reinterpret_cast<const float4*>(p)[i];
    v[4*i+0] = q.x; v[4*i+1] = q.y; v[4*i+2] = q.z; v[4*i+3] = q.w;
  }
}

__device__ __forceinline__ float dot16(const float w[16], const float v[16]){
  float a0 = 0.f, a1 = 0.f, a2 = 0.f, a3 = 0.f;
  #pragma unroll
  for (int j = 0; j < 4; j++){
    a0 = fmaf(w[4*j+0], v[4*j+0], a0);
    a1 = fmaf(w[4*j+1], v[4*j+1], a1);
    a2 = fmaf(w[4*j+2], v[4*j+2], a2);
    a3 = fmaf(w[4*j+3], v[4*j+3], a3);
  }
  return (a0 + a1) + (a2 + a3);
}

// ============================================================================
// Phase 1: backward LSTM scan + fused hproj. TWO batches per warp:
// lanes 0-15 = batch A, lanes 16-31 = batch B. Lane (half, lo) owns h-element
// lo of its batch and computes ALL FOUR of its gates in-lane (no shuffles).
// ============================================================================
__global__ __launch_bounds__(64)
void lstm_bwd_kernel(const float* __restrict__ x,
                     const float* __restrict__ Wih,
                     const float* __restrict__ Whh,
                     const float* __restrict__ bih,
                     const float* __restrict__ bhh,
                     const float* __restrict__ cW1,
                     const float* __restrict__ cb1)
{
  const int l  = threadIdx.x & 31;
  const int w  = threadIdx.x >> 5;
  const int lo = l & 15, half = l >> 4;
  const int b  = blockIdx.x * 4 + w * 2 + half;   // per-lane batch

  __shared__ __align__(16) float sH[2][32];       // [warp][batch-half*16 + elem]
  float* hbuf = sH[w];

  // gate rows for h-element lo: i=lo, f=16+lo, g=32+lo, o=48+lo
  float wi[16], wf[16], wg[16], wo[16];
  #pragma unroll
  for (int j = 0; j < 16; j++){
    wi[j] = Whh[(lo     )*16 + j];
    wf[j] = Whh[(lo + 16)*16 + j];
    wg[j] = Whh[(lo + 32)*16 + j];
    wo[j] = Whh[(lo + 48)*16 + j];
  }
  const float xi = Wih[lo], xf = Wih[lo+16], xg = Wih[lo+32], xo = Wih[lo+48];
  const float bi = bih[lo]    + bhh[lo];
  const float bf = bih[lo+16] + bhh[lo+16];
  const float bg = bih[lo+32] + bhh[lo+32];
  const float bo = bih[lo+48] + bhh[lo+48];

  // hproj row lo (h-columns of comb_W1) — same regs for both halves
  float wHp[16];
  #pragma unroll
  for (int j = 0; j < 16; j++) wHp[j] = cW1[lo*32 + j];
  const float bHp = cb1[lo];

  hbuf[l] = 0.f;
  float c = 0.f;
  __syncwarp();

  const float* xb = x + b;
  float* hpout = g_hproj + (size_t)b * 16 + lo;

  float xt = __ldg(xb + (size_t)(TL-1) * NB);   // prefetch first

  for (int t = TL - 1; t >= 0; --t){
    float xn = 0.f;
    if (t > 0) xn = __ldg(xb + (size_t)(t-1) * NB);   // off-chain prefetch

    float hv[16]; ldv16(hbuf + half*16, hv);

    // hproj for h[t+1] (currently in hv); skip first iteration
    float hp = bHp + dot16(wHp, hv);
    if (t != TL - 1) hpout[(size_t)(t+1) * NB16] = hp;

    float ai = fmaf(xt, xi, bi) + dot16(wi, hv);
    float af = fmaf(xt, xf, bf) + dot16(wf, hv);
    float ag = fmaf(xt, xg, bg) + dot16(wg, hv);
    float ao = fmaf(xt, xo, bo) + dot16(wo, hv);

    c = fmaf(sigf(af), c, sigf(ai) * tanh_fast(ag));
    float hn = sigf(ao) * tanh_fast(c);
    __syncwarp();               // all hbuf reads done
    hbuf[l] = hn;
    __syncwarp();
    xt = xn;
  }

  // epilogue: hproj[0] from final h
  {
    float hv[16]; ldv16(hbuf + half*16, hv);
    hpout[0] = bHp + dot16(wHp, hv);
  }
}

// ============================================================================
// Phase 2: DKF recurrence. TWO batches per warp. Lane (half, lo):
//   layers A and M: row lo for its batch (no duplicated work)
//   layer D: rows lo (mu) and 16+lo (logvar) for its batch -> z sample in-lane
// No shuffles anywhere. 3 syncwarps per step.
// ============================================================================
__global__ __launch_bounds__(64)
void dkf_rec_kernel(const float* __restrict__ eps,
                    const float* __restrict__ cW1,
                    const float* __restrict__ cW2, const float* __restrict__ cb2,
                    const float* __restrict__ eW1, const float* __restrict__ eb1,
                    const float* __restrict__ eW2, const float* __restrict__ eb2,
                    float* __restrict__ out)
{
  const int l  = threadIdx.x & 31;
  const int w  = threadIdx.x >> 5;
  const int lo = l & 15, half = l >> 4;
  const int b  = blockIdx.x * 4 + w * 2 + half;

  __shared__ __align__(16) float sm[2][96];
  float* SA = &sm[w][0];    // a1 (2x16)
  float* SC = &sm[w][32];   // e1 (2x16)
  float* SZ = &sm[w][64];   // z  (2x16)

  // layer A, z-columns of comb_W1, row lo
  float wAz[16];
  #pragma unroll
  for (int j = 0; j < 16; j++) wAz[j] = cW1[lo*32 + 16 + j];

  // fused M row lo: M = eW1 @ cW2 ; bM = eW1 @ cb2 + eb1
  float wM[16];
  float bM = eb1[lo];
  {
    float e1w[8];
    #pragma unroll
    for (int k = 0; k < 8; k++) e1w[k] = eW1[lo*8 + k];
    #pragma unroll
    for (int c = 0; c < 16; c++){
      float acc = 0.f;
      #pragma unroll
      for (int k = 0; k < 8; k++) acc = fmaf(e1w[k], cW2[k*16 + c], acc);
      wM[c] = acc;
    }
    #pragma unroll
    for (int k = 0; k < 8; k++) bM = fmaf(e1w[k], cb2[k], bM);
  }

  // enc2: rows lo (mu) and 16+lo (logvar)
  float wDa[16], wDb[16];
  #pragma unroll
  for (int j = 0; j < 16; j++){
    wDa[j] = eW2[lo*16 + j];
    wDb[j] = eW2[(lo+16)*16 + j];
  }
  const float bDa = eb2[lo], bDb = eb2[lo+16];

  SZ[l] = 0.f;      // z0
  __syncwarp();

  const float* hpp = g_hproj + (size_t)b * 16 + lo;
  const float* epp = eps     + (size_t)b * 16 + lo;
  float*       zsp = g_zseq  + (size_t)b * 16 + lo;
  float*       outp = out    + (size_t)b * 66;

  float hpv  = __ldg(hpp);
  float epsv = __ldg(epp);

  for (int t = 0; t < TL; ++t){
    // off-chain prefetch for next step
    float hpn = 0.f, epsn = 0.f;
    if (t + 1 < TL){
      hpn  = __ldg(hpp + (size_t)(t+1) * NB16);
      epsn = __ldg(epp + (size_t)(t+1) * NB16);
    }

    // ---- Layer A ----
    float zv[16]; ldv16(SZ + half*16, zv);
    float a1 = tanh_fast(hpv + dot16(wAz, zv));
    SA[l] = a1;
    __syncwarp();

    // ---- Fused B+C ----
    float av[16]; ldv16(SA + half*16, av);
    float e1 = tanh_fast(bM + dot16(wM, av));
    SC[l] = e1;
    __syncwarp();

    // ---- Layer D + sample (all in-lane) ----
    float ev[16]; ldv16(SC + half*16, ev);
    float e2a = bDa + dot16(wDa, ev);      // mu_z[lo]
    float e2b = bDb + dot16(wDb, ev);      // logvar_z[lo]
    outp[2 + lo]  = e2a;                   // off-chain stores
    outp[18 + lo] = e2b;
    float znew = fmaf(epsv, __expf(0.5f * e2b), e2a);
    SZ[l] = znew;
    zsp[(size_t)t * NB16] = znew;
    __syncwarp();

    hpv = hpn; epsv = epsn;
    outp += (size_t)NB * 66;
  }
}

// ============================================================================
// Phase 3: decoder + transition. Fully parallel over all (t,b) positions.
// ============================================================================
#define OD_W1 0
#define OD_B1 256
#define OD_W2 272
#define OD_B2 304
#define OT_W1 308
#define OT_B1 564
#define OT_W2 580
#define OT_B2 1092
#define SW_TOT 1124

__device__ __forceinline__ float sdot16(const float* srow, const float v[16]){
  float a0 = 0.f, a1 = 0.f, a2 = 0.f, a3 = 0.f;
  #pragma unroll
  for (int j = 0; j < 4; j++){
    float4 q = reinterpret_cast<const float4*>(srow)[j];
    a0 = fmaf(q.x, v[4*j+0], a0);
    a1 = fmaf(q.y, v[4*j+1], a1);
    a2 = fmaf(q.z, v[4*j+2], a2);
    a3 = fmaf(q.w, v[4*j+3], a3);
  }
  return (a0 + a1) + (a2 + a3);
}

__global__ __launch_bounds__(256)
void dectr_kernel(const float* __restrict__ dW1, const float* __restrict__ db1,
                  const float* __restrict__ dW2, const float* __restrict__ db2,
                  const float* __restrict__ tW1, const float* __restrict__ tb1,
                  const float* __restrict__ tW2, const float* __restrict__ tb2,
                  float* __restrict__ out)
{
  __shared__ __align__(16) float s[SW_TOT];
  const int tid = threadIdx.x;
  for (int i = tid; i < 256; i += 256) s[OD_W1 + i] = dW1[i];
  if (tid < 16)  s[OD_B1 + tid] = db1[tid];
  if (tid < 32)  s[OD_W2 + tid] = dW2[tid];
  if (tid < 2)   s[OD_B2 + tid] = db2[tid];
  for (int i = tid; i < 256; i += 256) s[OT_W1 + i] = tW1[i];
  if (tid < 16)  s[OT_B1 + tid] = tb1[tid];
  for (int i = tid; i < 512; i += 256) s[OT_W2 + i] = tW2[i];
  if (tid < 32)  s[OT_B2 + tid] = tb2[tid];
  __syncthreads();

  const size_t pos = (size_t)blockIdx.x * 256 + tid;   // t*NB + b
  const float* zp_ptr = g_zseq + pos * 16;

  float z[16]; ldv16(zp_ptr, z);
  float zp[16];
  if (pos >= NB){ ldv16(zp_ptr - (size_t)NB * 16, zp); }
  else {
    #pragma unroll
    for (int j = 0; j < 16; j++) zp[j] = 0.f;
  }

  float* ob = out + pos * 66;

  float d1[16];
  #pragma unroll
  for (int r = 0; r < 16; r++)
    d1[r] = tanh_fast(s[OD_B1 + r] + sdot16(&s[OD_W1 + r*16], z));
  float2 dx;
  dx.x = s[OD_B2 + 0] + sdot16(&s[OD_W2 + 0],  d1);
  dx.y = s[OD_B2 + 1] + sdot16(&s[OD_W2 + 16], d1);
  *reinterpret_cast<float2*>(ob) = dx;    // mu_x, logvar_x

  float t1[16];
  #pragma unroll
  for (int r = 0; r < 16; r++)
    t1[r] = tanh_fast(s[OT_B1 + r] + sdot16(&s[OT_W1 + r*16], zp));
  #pragma unroll
  for (int r = 0; r < 32; r += 2){
    float2 tv;
    tv.x = s[OT_B2 + r]     + sdot16(&s[OT_W2 + r*16],     t1);
    tv.y = s[OT_B2 + r + 1] + sdot16(&s[OT_W2 + (r+1)*16], t1);
    *reinterpret_cast<float2*>(ob + 34 + r) = tv;   // mu_tr / logvar_tr
  }
}

extern "C" void kernel_launch(void* const* d_in, const int* in_sizes, int n_in,
                              void* d_out, int out_size)
{
  const float* x   = (const float*)d_in[0];
  const float* eps = (const float*)d_in[1];
  const float* Wih = (const float*)d_in[2];
  const float* Whh = (const float*)d_in[3];
  const float* bih = (const float*)d_in[4];
  const float* bhh = (const float*)d_in[5];
  const float* cW1 = (const float*)d_in[6];
  const float* cb1 = (const float*)d_in[7];
  const float* cW2 = (const float*)d_in[8];
  const float* cb2 = (const float*)d_in[9];
  const float* eW1 = (const float*)d_in[10];
  const float* eb1 = (const float*)d_in[11];
  const float* eW2 = (const float*)d_in[12];
  const float* eb2 = (const float*)d_in[13];
  const float* dW1 = (const float*)d_in[14];
  const float* db1 = (const float*)d_in[15];
  const float* dW2 = (const float*)d_in[16];
  const float* db2 = (const float*)d_in[17];
  const float* tW1 = (const float*)d_in[18];
  const float* tb1 = (const float*)d_in[19];
  const float* tW2 = (const float*)d_in[20];
  const float* tb2 = (const float*)d_in[21];
  float* out = (float*)d_out;

  lstm_bwd_kernel<<<NB/4, 64>>>(x, Wih, Whh, bih, bhh, cW1, cb1);
  dkf_rec_kernel<<<NB/4, 64>>>(eps, cW1, cW2, cb2, eW1, eb1, eW2, eb2, out);
  dectr_kernel<<<(TL*NB)/256, 256>>>(dW1, db1, dW2, db2, tW1, tb1, tW2, tb2, out);
}

// round 5
// speedup vs baseline: 1.3377x; 1.3377x over previous
#include <cuda_runtime.h>
#include <cstdint>
#include <cstddef>

#define TL 512
#define NB 2048
#define NB16 (NB*16)
#define FULL 0xffffffffu

// scratch: hproj_seq and z_seq, each T*B*16 floats = 64 MiB
__device__ float g_hproj[(size_t)TL * NB * 16];
__device__ float g_zseq[(size_t)TL * NB * 16];

__device__ __forceinline__ float sigf(float x){
  return __fdividef(1.f, 1.f + __expf(-x));
}
__device__ __forceinline__ float tanh_fast(float x){
  return __fdividef(2.f, 1.f + __expf(-2.f * x)) - 1.f;
}

// ---- packed f32x2 helpers (Blackwell FFMA2) ----
__device__ __forceinline__ uint64_t pk2(float lo, float hi){
  uint64_t r; asm("mov.b64 %0, {%1, %2};" : "=l"(r) : "f"(lo), "f"(hi)); return r;
}
__device__ __forceinline__ uint64_t fma2(uint64_t a, uint64_t b, uint64_t c){
  uint64_t d; asm("fma.rn.f32x2 %0, %1, %2, %3;" : "=l"(d) : "l"(a), "l"(b), "l"(c));
  return d;
}
__device__ __forceinline__ float dot16p(const uint64_t w[8], const uint64_t v[8]){
  const uint64_t z = 0;       // (+0.f, +0.f)
  uint64_t a0 = fma2(w[0], v[0], z);
  uint64_t a1 = fma2(w[1], v[1], z);
  a0 = fma2(w[2], v[2], a0);
  a1 = fma2(w[3], v[3], a1);
  a0 = fma2(w[4], v[4], a0);
  a1 = fma2(w[5], v[5], a1);
  a0 = fma2(w[6], v[6], a0);
  a1 = fma2(w[7], v[7], a1);
  uint64_t s; asm("add.rn.f32x2 %0, %1, %2;" : "=l"(s) : "l"(a0), "l"(a1));
  float lo, hi; asm("mov.b64 {%0, %1}, %2;" : "=f"(lo), "=f"(hi) : "l"(s));
  return lo + hi;
}
// load 16 floats (16B-aligned smem) as 8 packed f32x2
__device__ __forceinline__ void ldv8p(const float* p, uint64_t v[8]){
  #pragma unroll
  for (int i = 0; i < 4; i++){
    ulonglong2 q = reinterpret_cast<const ulonglong2*>(p)[i];
    v[2*i] = q.x; v[2*i+1] = q.y;
  }
}
__device__ __forceinline__ void ldv16(const float* p, float v[16]){
  #pragma unroll
  for (int i = 0; i < 4; i++){
    float4 q = reinterpret_cast<const float4*>(p)[i];
    v[4*i+0] = q.x; v[4*i+1] = q.y; v[4*i+2] = q.z; v[4*i+3] = q.w;
  }
}

// ============================================================================
// Phase 1: backward LSTM scan + fused hproj. One warp per batch element.
// lanes 0-15: rows l (i-gate) and l+32 (g); lanes 16-31: rows l (f) and l+32 (o).
// All dot16s in packed FFMA2.
// ============================================================================
__global__ __launch_bounds__(64)
void lstm_bwd_kernel(const float* __restrict__ x,
                     const float* __restrict__ Wih,
                     const float* __restrict__ Whh,
                     const float* __restrict__ bih,
                     const float* __restrict__ bhh,
                     const float* __restrict__ cW1,
                     const float* __restrict__ cb1)
{
  const int l = threadIdx.x & 31;
  const int w = threadIdx.x >> 5;
  const int b = blockIdx.x * 2 + w;
  const int lo = l & 15;

  __shared__ __align__(16) float sH[2][16];
  float* hbuf = sH[w];

  const int r0 = l, r1 = l + 32;
  uint64_t w0[8], w1[8], wHp[8];
  #pragma unroll
  for (int j = 0; j < 8; j++){
    w0[j]  = pk2(Whh[r0*16 + 2*j],     Whh[r0*16 + 2*j + 1]);
    w1[j]  = pk2(Whh[r1*16 + 2*j],     Whh[r1*16 + 2*j + 1]);
    wHp[j] = pk2(cW1[lo*32 + 2*j],     cW1[lo*32 + 2*j + 1]);
  }
  const float wx0 = Wih[r0], wx1 = Wih[r1];
  const float b0 = bih[r0] + bhh[r0];
  const float b1 = bih[r1] + bhh[r1];
  const float bHp = cb1[lo];

  if (l < 16) hbuf[l] = 0.f;
  float c = 0.f;
  __syncwarp();

  const float* xb = x + b;
  float* hpout = g_hproj + (size_t)b * 16 + lo;

  float xt = __ldg(xb + (size_t)(TL-1) * NB);   // prefetch first

  for (int t = TL - 1; t >= 0; --t){
    float xn = 0.f;
    if (t > 0) xn = __ldg(xb + (size_t)(t-1) * NB);   // off-chain prefetch

    uint64_t hv[8]; ldv8p(hbuf, hv);

    // hproj for h[t+1] (currently in hbuf); skip first iteration
    float hp = bHp + dot16p(wHp, hv);
    if (l < 16 && t != TL - 1)
      hpout[(size_t)(t+1) * NB16] = hp;

    float a0 = fmaf(xt, wx0, b0) + dot16p(w0, hv);
    float a1 = fmaf(xt, wx1, b1) + dot16p(w1, hv);

    float p, q = 0.f;
    if (l < 16) { p = sigf(a0) * tanh_fast(a1); }     // sig(i)*tanh(g)
    else        { p = sigf(a0); q = sigf(a1); }       // sig(f), sig(o)
    float pf = __shfl_xor_sync(FULL, p, 16);
    float qo = __shfl_xor_sync(FULL, q, 16);
    __syncwarp();                                     // hbuf reads done
    if (l < 16){
      c = fmaf(pf, c, p);
      float hn = qo * tanh_fast(c);
      hbuf[l] = hn;
    }
    __syncwarp();
    xt = xn;
  }

  // epilogue: hproj[0] from final h
  {
    uint64_t hv[8]; ldv8p(hbuf, hv);
    float hp = bHp + dot16p(wHp, hv);
    if (l < 16) hpout[0] = hp;
  }
}

// ============================================================================
// Phase 2: DKF recurrence. One warp per batch, full-row lane ownership,
// 4-deep register-ring prefetch of hproj/eps (DRAM latency cover),
// packed FFMA2 dots. 3 syncwarps per step.
// ============================================================================
__global__ __launch_bounds__(64)
void dkf_rec_kernel(const float* __restrict__ eps,
                    const float* __restrict__ cW1,
                    const float* __restrict__ cW2, const float* __restrict__ cb2,
                    const float* __restrict__ eW1, const float* __restrict__ eb1,
                    const float* __restrict__ eW2, const float* __restrict__ eb2,
                    float* __restrict__ out)
{
  const int l = threadIdx.x & 31;
  const int w = threadIdx.x >> 5;
  const int b = blockIdx.x * 2 + w;
  const int lo = l & 15;

  __shared__ __align__(16) float sm[2][48];
  float* SA = &sm[w][0];    // a1 (16)
  float* SC = &sm[w][16];   // e1 (16)
  float* SZ = &sm[w][32];   // z  (16)

  // layer A, z-columns of comb_W1, row lo (duplicated across halves)
  uint64_t wAz[8];
  #pragma unroll
  for (int j = 0; j < 8; j++)
    wAz[j] = pk2(cW1[lo*32 + 16 + 2*j], cW1[lo*32 + 16 + 2*j + 1]);

  // fused M row lo: M = eW1 @ cW2 ; bM = eW1 @ cb2 + eb1
  uint64_t wM[8];
  float bM = eb1[lo];
  {
    float e1w[8];
    #pragma unroll
    for (int k = 0; k < 8; k++) e1w[k] = eW1[lo*8 + k];
    #pragma unroll
    for (int cc = 0; cc < 8; cc++){
      float accx = 0.f, accy = 0.f;
      #pragma unroll
      for (int k = 0; k < 8; k++){
        accx = fmaf(e1w[k], cW2[k*16 + 2*cc],     accx);
        accy = fmaf(e1w[k], cW2[k*16 + 2*cc + 1], accy);
      }
      wM[cc] = pk2(accx, accy);
    }
    #pragma unroll
    for (int k = 0; k < 8; k++) bM = fmaf(e1w[k], cb2[k], bM);
  }

  // enc2 (32x16): lane l owns row l
  uint64_t wD[8];
  #pragma unroll
  for (int j = 0; j < 8; j++)
    wD[j] = pk2(eW2[l*16 + 2*j], eW2[l*16 + 2*j + 1]);
  const float bD = eb2[l];

  if (l < 16) SZ[lo] = 0.f;      // z0
  __syncwarp();

  const float* hpp = g_hproj + (size_t)b * 16 + lo;
  const float* epp = eps     + (size_t)b * 16 + lo;
  float*       zsp = g_zseq  + (size_t)b * 16 + lo;
  float*       outp = out    + (size_t)b * 66;

  // ---- 4-deep prefetch ring ----
  float hp0 = __ldg(hpp);
  float hp1 = __ldg(hpp + (size_t)1 * NB16);
  float hp2 = __ldg(hpp + (size_t)2 * NB16);
  float hp3 = __ldg(hpp + (size_t)3 * NB16);
  float ep0 = __ldg(epp);
  float ep1 = __ldg(epp + (size_t)1 * NB16);
  float ep2 = __ldg(epp + (size_t)2 * NB16);
  float ep3 = __ldg(epp + (size_t)3 * NB16);

  #define DKF_STEP(T, HPV, EPSV)                                          \
  {                                                                       \
    uint64_t zv[8]; ldv8p(SZ, zv);                                        \
    float a1 = tanh_fast((HPV) + dot16p(wAz, zv));                        \
    if (l < 16) SA[lo] = a1;                                              \
    __syncwarp();                                                         \
    uint64_t av[8]; ldv8p(SA, av);                                        \
    float e1 = tanh_fast(bM + dot16p(wM, av));                            \
    if (l < 16) SC[lo] = e1;                                              \
    __syncwarp();                                                         \
    uint64_t ev[8]; ldv8p(SC, ev);                                        \
    float e2 = bD + dot16p(wD, ev);                                       \
    outp[2 + l] = e2;                                                     \
    float lvz = __shfl_xor_sync(FULL, e2, 16);                            \
    float znew = fmaf((EPSV), __expf(0.5f * lvz), e2);                    \
    if (l < 16){                                                          \
      SZ[lo] = znew;                                                      \
      zsp[(size_t)(T) * NB16] = znew;                                     \
    }                                                                     \
    __syncwarp();                                                         \
    outp += (size_t)NB * 66;                                              \
  }

  #pragma unroll 1
  for (int t = 0; t < TL; t += 4){
    int t4 = t + 4; if (t4 > TL-1) t4 = TL-1;
    int t5 = t + 5; if (t5 > TL-1) t5 = TL-1;
    int t6 = t + 6; if (t6 > TL-1) t6 = TL-1;
    int t7 = t + 7; if (t7 > TL-1) t7 = TL-1;

    float hpa = __ldg(hpp + (size_t)t4 * NB16);
    float epa = __ldg(epp + (size_t)t4 * NB16);
    DKF_STEP(t + 0, hp0, ep0);
    hp0 = hpa; ep0 = epa;

    float hpb = __ldg(hpp + (size_t)t5 * NB16);
    float epb = __ldg(epp + (size_t)t5 * NB16);
    DKF_STEP(t + 1, hp1, ep1);
    hp1 = hpb; ep1 = epb;

    float hpc = __ldg(hpp + (size_t)t6 * NB16);
    float epc = __ldg(epp + (size_t)t6 * NB16);
    DKF_STEP(t + 2, hp2, ep2);
    hp2 = hpc; ep2 = epc;

    float hpd = __ldg(hpp + (size_t)t7 * NB16);
    float epd = __ldg(epp + (size_t)t7 * NB16);
    DKF_STEP(t + 3, hp3, ep3);
    hp3 = hpd; ep3 = epd;
  }
  #undef DKF_STEP
}

// ============================================================================
// Phase 3: decoder + transition. Fully parallel over all (t,b) positions.
// ============================================================================
#define OD_W1 0
#define OD_B1 256
#define OD_W2 272
#define OD_B2 304
#define OT_W1 308
#define OT_B1 564
#define OT_W2 580
#define OT_B2 1092
#define SW_TOT 1124

__device__ __forceinline__ float sdot16(const float* srow, const float v[16]){
  float a0 = 0.f, a1 = 0.f, a2 = 0.f, a3 = 0.f;
  #pragma unroll
  for (int j = 0; j < 4; j++){
    float4 q = reinterpret_cast<const float4*>(srow)[j];
    a0 = fmaf(q.x, v[4*j+0], a0);
    a1 = fmaf(q.y, v[4*j+1], a1);
    a2 = fmaf(q.z, v[4*j+2], a2);
    a3 = fmaf(q.w, v[4*j+3], a3);
  }
  return (a0 + a1) + (a2 + a3);
}

__global__ __launch_bounds__(256)
void dectr_kernel(const float* __restrict__ dW1, const float* __restrict__ db1,
                  const float* __restrict__ dW2, const float* __restrict__ db2,
                  const float* __restrict__ tW1, const float* __restrict__ tb1,
                  const float* __restrict__ tW2, const float* __restrict__ tb2,
                  float* __restrict__ out)
{
  __shared__ __align__(16) float s[SW_TOT];
  const int tid = threadIdx.x;
  for (int i = tid; i < 256; i += 256) s[OD_W1 + i] = dW1[i];
  if (tid < 16)  s[OD_B1 + tid] = db1[tid];
  if (tid < 32)  s[OD_W2 + tid] = dW2[tid];
  if (tid < 2)   s[OD_B2 + tid] = db2[tid];
  for (int i = tid; i < 256; i += 256) s[OT_W1 + i] = tW1[i];
  if (tid < 16)  s[OT_B1 + tid] = tb1[tid];
  for (int i = tid; i < 512; i += 256) s[OT_W2 + i] = tW2[i];
  if (tid < 32)  s[OT_B2 + tid] = tb2[tid];
  __syncthreads();

  const size_t pos = (size_t)blockIdx.x * 256 + tid;   // t*NB + b
  const float* zp_ptr = g_zseq + pos * 16;

  float z[16]; ldv16(zp_ptr, z);
  float zp[16];
  if (pos >= NB){ ldv16(zp_ptr - (size_t)NB * 16, zp); }
  else {
    #pragma unroll
    for (int j = 0; j < 16; j++) zp[j] = 0.f;
  }

  float* ob = out + pos * 66;

  float d1[16];
  #pragma unroll
  for (int r = 0; r < 16; r++)
    d1[r] = tanh_fast(s[OD_B1 + r] + sdot16(&s[OD_W1 + r*16], z));
  float2 dx;
  dx.x = s[OD_B2 + 0] + sdot16(&s[OD_W2 + 0],  d1);
  dx.y = s[OD_B2 + 1] + sdot16(&s[OD_W2 + 16], d1);
  *reinterpret_cast<float2*>(ob) = dx;    // mu_x, logvar_x

  float t1[16];
  #pragma unroll
  for (int r = 0; r < 16; r++)
    t1[r] = tanh_fast(s[OT_B1 + r] + sdot16(&s[OT_W1 + r*16], zp));
  #pragma unroll
  for (int r = 0; r < 32; r += 2){
    float2 tv;
    tv.x = s[OT_B2 + r]     + sdot16(&s[OT_W2 + r*16],     t1);
    tv.y = s[OT_B2 + r + 1] + sdot16(&s[OT_W2 + (r+1)*16], t1);
    *reinterpret_cast<float2*>(ob + 34 + r) = tv;   // mu_tr / logvar_tr
  }
}

extern "C" void kernel_launch(void* const* d_in, const int* in_sizes, int n_in,
                              void* d_out, int out_size)
{
  const float* x   = (const float*)d_in[0];
  const float* eps = (const float*)d_in[1];
  const float* Wih = (const float*)d_in[2];
  const float* Whh = (const float*)d_in[3];
  const float* bih = (const float*)d_in[4];
  const float* bhh = (const float*)d_in[5];
  const float* cW1 = (const float*)d_in[6];
  const float* cb1 = (const float*)d_in[7];
  const float* cW2 = (const float*)d_in[8];
  const float* cb2 = (const float*)d_in[9];
  const float* eW1 = (const float*)d_in[10];
  const float* eb1 = (const float*)d_in[11];
  const float* eW2 = (const float*)d_in[12];
  const float* eb2 = (const float*)d_in[13];
  const float* dW1 = (const float*)d_in[14];
  const float* db1 = (const float*)d_in[15];
  const float* dW2 = (const float*)d_in[16];
  const float* db2 = (const float*)d_in[17];
  const float* tW1 = (const float*)d_in[18];
  const float* tb1 = (const float*)d_in[19];
  const float* tW2 = (const float*)d_in[20];
  const float* tb2 = (const float*)d_in[21];
  float* out = (float*)d_out;

  lstm_bwd_kernel<<<NB/2, 64>>>(x, Wih, Whh, bih, bhh, cW1, cb1);
  dkf_rec_kernel<<<NB/2, 64>>>(eps, cW1, cW2, cb2, eW1, eb1, eW2, eb2, out);
  dectr_kernel<<<(TL*NB)/256, 256>>>(dW1, db1, dW2, db2, tW1, tb1, tW2, tb2, out);
}